// round 11
// baseline (speedup 1.0000x reference)
#include <cuda_runtime.h>
#include <cuda_fp16.h>
#include <cstdint>

// ---------------------------------------------------------------------------
// Problem constants
// ---------------------------------------------------------------------------
#define HH    192
#define WW    192
#define NPIX  (HH*WW)          // 36864
#define NB    8                // 2 halves * batch 4

// ---------------------------------------------------------------------------
// Device scratch: only v round-trips.
// ---------------------------------------------------------------------------
__device__ float g_v[8*4*NPIX*32];

// ---------------------------------------------------------------------------
// fp16 helpers (base-ISA mma.sync m16n8k16)
// ---------------------------------------------------------------------------
__device__ __forceinline__ uint32_t pkh2(float a, float b) {
    __half2 h = __floats2half2_rn(a, b);   // low half = a
    return *reinterpret_cast<uint32_t*>(&h);
}
__device__ __forceinline__ void mma_f16(float* c, const uint4& a, const uint2& b) {
    asm volatile(
        "mma.sync.aligned.m16n8k16.row.col.f32.f16.f16.f32 "
        "{%0,%1,%2,%3}, {%4,%5,%6,%7}, {%8,%9}, {%0,%1,%2,%3};"
        : "+f"(c[0]), "+f"(c[1]), "+f"(c[2]), "+f"(c[3])
        : "r"(a.x), "r"(a.y), "r"(a.z), "r"(a.w), "r"(b.x), "r"(b.y));
}

#define B_KSTRIDE 1026   // b32 per kstep block

// ---- fused-kernel smem map (float units) ------------------------------------
// [0 .. 4096)        A tile (64 pix x 128 k fp16 frags)
// [4096 .. 8200)     B chunk (4 ksteps)
// [8200 .. 10880)    pad — vs_h overlay region is [0, 10880) floats
//                    (vs_h: 4 heads x (4x34 halo) x 40 halves = 21760 halves)
// [10880 .. 16000)   Ks_h: 4 heads x 64 pix x 40 halves
// [16000 .. 21120)   Qs_h: 4 heads x 64 pix x 40 halves
// [21120 .. 22144)   aw: softmax weights [head][win][tok][4] fp32
// [22144 .. 23296)   lepe weights [head][tap][hd] fp32
// [23296 .. 23424)   lepe bias
// [23424 .. 23488)   attn bias
#define SMF_B    4096
#define SMF_KH   10880
#define SMF_QH   16000
#define SMF_AW   21120
#define SMF_LW   22144
#define SMF_LB   23296
#define SMF_BIAS 23424
#define SM_TOT_F (23488*4)     // 93952 B -> 2 CTAs/SM

// ---- v-kernel smem map -------------------------------------------------------
#define SMF_VB  4096
#define SMF_VC  8200
#define SM_TOT_V (17416*4)     // 69664 B -> 3 CTAs/SM

// ---------------------------------------------------------------------------
// B chunk staging (256 threads): weights [o(128)][k(128)] fp32 -> fp16 frag
// ---------------------------------------------------------------------------
__device__ __forceinline__ void stage_b_chunk(uint32_t* __restrict__ Bc,
                                              const float* __restrict__ w,
                                              int c, int tid)
{
    #pragma unroll
    for (int it = 0; it < 8; ++it) {
        int i   = it*256 + tid;      // 0..2047
        int o   = i >> 4;            // 0..127
        int k4l = i & 15;
        float4 v = __ldg((const float4*)(w + (size_t)o*128) + (c*16 + k4l));
        int ksl = k4l >> 2;
        int kc  = (k4l & 3) * 4;
        int tg0 = (kc >> 1) & 3;
        int r   = kc >> 3;
        uint32_t base = (uint32_t)(ksl*B_KSTRIDE + (o>>3)*64 + ((o&7)*4 + tg0)*2 + r);
        Bc[base    ] = pkh2(v.x, v.y);
        Bc[base + 2] = pkh2(v.z, v.w);
    }
}

// ---------------------------------------------------------------------------
// MMA over one 4-kstep chunk; 8 warps: warp tile 32(M) x 32(N), M total 64
// ---------------------------------------------------------------------------
__device__ __forceinline__ void mma_chunk4(float acc[2][4][4],
                                           const uint32_t* __restrict__ As,
                                           const uint32_t* __restrict__ Bc,
                                           int ks0, int warp_m, int warp_n, int lane)
{
    #pragma unroll
    for (int l = 0; l < 4; ++l) {
        const int kg = ks0 + l;
        uint4 a[2];
        #pragma unroll
        for (int i = 0; i < 2; ++i) {
            uint32_t u = (uint32_t)((kg*4 + warp_m*2 + i)*32 + lane);
            u ^= (u >> 3) & 7;
            a[i] = *(const uint4*)(As + (size_t)u*4);
        }
        uint2 bf[4];
        #pragma unroll
        for (int j = 0; j < 4; ++j)
            bf[j] = *(const uint2*)(Bc + l*B_KSTRIDE + (warp_n*4 + j)*64 + lane*2);
        #pragma unroll
        for (int i = 0; i < 2; ++i)
            #pragma unroll
            for (int j = 0; j < 4; ++j)
                mma_f16(acc[i][j], a[i], bf[j]);
    }
}

__device__ __forceinline__ void acc_zero(float acc[2][4][4]) {
    #pragma unroll
    for (int i = 0; i < 2; ++i)
        #pragma unroll
        for (int j = 0; j < 4; ++j)
            #pragma unroll
            for (int e = 0; e < 4; ++e) acc[i][j][e] = 0.0f;
}

// acc -> Cs fp32 [head(4)][pix 64][36]   (v_kernel epilogue)
__device__ __forceinline__ void write_c_all(const float acc[2][4][4],
                                            float* __restrict__ Cs,
                                            int warp_m, int warp_n, int lane)
{
    const int g  = lane >> 2;
    const int tg = lane & 3;
    #pragma unroll
    for (int i = 0; i < 2; ++i) {
        int pl = warp_m*32 + i*16 + g;
        #pragma unroll
        for (int j = 0; j < 4; ++j) {
            int o0 = warp_n*32 + j*8 + 2*tg;
            int h0 = o0 & 3, h1 = (o0 + 1) & 3;
            int hd = o0 >> 2;
            Cs[(h0*64 + pl    )*36 + hd] = acc[i][j][0];
            Cs[(h1*64 + pl    )*36 + hd] = acc[i][j][1];
            Cs[(h0*64 + pl + 8)*36 + hd] = acc[i][j][2];
            Cs[(h1*64 + pl + 8)*36 + hd] = acc[i][j][3];
        }
    }
}

// acc -> fp16 [head(4)][pix 64][stride 40]  (Ks_h / Qs_h)
__device__ __forceinline__ void write_kq_h(const float acc[2][4][4],
                                           __half* __restrict__ K,
                                           int warp_m, int warp_n, int lane)
{
    const int g  = lane >> 2;
    const int tg = lane & 3;
    #pragma unroll
    for (int i = 0; i < 2; ++i) {
        int pl = warp_m*32 + i*16 + g;
        #pragma unroll
        for (int j = 0; j < 4; ++j) {
            int o0 = warp_n*32 + j*8 + 2*tg;
            int h0 = o0 & 3, h1 = (o0 + 1) & 3;
            int hd = o0 >> 2;
            K[(h0*64 + pl    )*40 + hd] = __float2half_rn(acc[i][j][0]);
            K[(h1*64 + pl    )*40 + hd] = __float2half_rn(acc[i][j][1]);
            K[(h0*64 + pl + 8)*40 + hd] = __float2half_rn(acc[i][j][2]);
            K[(h1*64 + pl + 8)*40 + hd] = __float2half_rn(acc[i][j][3]);
        }
    }
}

// ---------------------------------------------------------------------------
// A staging: 64 pixels x 128 k -> fp16 fragment-major + swizzle.
// ---------------------------------------------------------------------------
__device__ __forceinline__ void stage_a(uint32_t* __restrict__ As,
                                        const float* __restrict__ xb,
                                        int pix, int kh)
{
    const int mtile   = pix >> 4;
    const int g       = pix & 7;
    const int rowhalf = (pix >> 3) & 1;
    #pragma unroll 4
    for (int k2 = 0; k2 < 32; k2 += 2) {
        int k = kh*32 + k2;
        float f0 = __ldg(xb + (size_t)k2 * NPIX);
        float f1 = __ldg(xb + (size_t)(k2+1) * NPIX);
        int kstep = k >> 4;
        int kc    = k & 15;
        int colhalf = kc >> 3;
        int tg      = (kc >> 1) & 3;
        uint32_t u = (uint32_t)((kstep*4 + mtile)*32 + g*4 + tg);
        u ^= (u >> 3) & 7;
        As[u*4 + colhalf*2 + rowhalf] = pkh2(f0, f1);
    }
}

// ---------------------------------------------------------------------------
// Kernel 1: v = 1x1 conv (fp16 GEMM), M=64 linear blocks, 3 CTAs/SM
// ---------------------------------------------------------------------------
__global__ void __launch_bounds__(256, 3)
v_kernel(const float* __restrict__ x, const float* __restrict__ qkv_w)
{
    extern __shared__ __align__(16) float smf[];
    uint32_t* As = (uint32_t*)smf;
    uint32_t* Bc = (uint32_t*)(smf + SMF_VB);
    float*    Cs = smf + SMF_VC;

    const int tid    = threadIdx.x;
    const int lane   = tid & 31;
    const int wid    = tid >> 5;
    const int warp_m = wid >> 2;
    const int warp_n = wid & 3;
    const int n      = blockIdx.y;
    const int half   = n >> 2;
    const int b      = n & 3;
    const int p0     = blockIdx.x * 64;
    const size_t n4  = (size_t)n * 4;

    {
        const int pix = tid & 63;
        const int kh  = tid >> 6;
        const float* xb = x + ((size_t)(b*256 + half*128 + kh*32)) * NPIX + p0 + pix;
        stage_a(As, xb, pix, kh);
    }

    float acc[2][4][4];
    acc_zero(acc);
    #pragma unroll 1
    for (int c = 0; c < 2; ++c) {
        stage_b_chunk(Bc, qkv_w + 32768, c, tid);
        __syncthreads();
        mma_chunk4(acc, As, Bc, c*4, warp_m, warp_n, lane);
        __syncthreads();
    }

    write_c_all(acc, Cs, warp_m, warp_n, lane);
    __syncthreads();

    {
        int h   = tid >> 6;
        int pix = tid & 63;
        const float4* src = (const float4*)(Cs + (size_t)(h*64 + pix)*36);
        float4* d = (float4*)(g_v + ((n4 + h)*NPIX + (size_t)(p0 + pix))*32);
        #pragma unroll
        for (int c = 0; c < 8; ++c) d[c] = src[c];
    }
}

// ---------------------------------------------------------------------------
// Kernel 2: fused q,k GEMM + split-phase window attention + LePE.
// CTA = 2 rows x 32 cols, 256 threads, 2 CTAs/SM.
// ---------------------------------------------------------------------------
__global__ void __launch_bounds__(256, 2)
qkv_attn_kernel(const float* __restrict__ x, const float* __restrict__ qkv_w,
                const float* __restrict__ lepe_w, const float* __restrict__ lepe_b,
                const float* __restrict__ bias_table, const int* __restrict__ rel_idx,
                float* __restrict__ out)
{
    extern __shared__ __align__(16) float smf[];
    uint32_t* As   = (uint32_t*)smf;
    uint32_t* Bc   = (uint32_t*)(smf + SMF_B);
    __half*   vs_h = (__half*)smf;                // overlays A+B after GEMMs
    __half*   Ks_h = (__half*)(smf + SMF_KH);
    __half*   Qs_h = (__half*)(smf + SMF_QH);

    const int tid    = threadIdx.x;
    const int lane   = tid & 31;
    const int wid    = tid >> 5;
    const int warp_m = wid >> 2;
    const int warp_n = wid & 3;
    const int n      = blockIdx.z;
    const int half   = n >> 2;
    const int b      = n & 3;
    const int x0     = blockIdx.x * 32;
    const int y0     = blockIdx.y * 2;
    const size_t n4  = (size_t)n * 4;

    // stage per-head constants from raw inputs (tiny, L2-resident)
    for (int idx = tid; idx < 1152; idx += 256) {
        int head = idx / 288;
        int r    = idx % 288;
        int tap  = r >> 5;
        int hd   = r & 31;
        smf[SMF_LW + idx] = __ldg(&lepe_w[(hd*4 + head)*9 + tap]);
    }
    if (tid < 128) {
        smf[SMF_LB + tid] = __ldg(&lepe_b[(tid & 31)*4 + (tid >> 5)]);
    } else if (tid < 192) {
        int t2 = tid - 128;
        int head = t2 >> 4, ij = t2 & 15;
        smf[SMF_BIAS + t2] = __ldg(&bias_table[__ldg(&rel_idx[ij])*4 + head]);
    }

    // stage A: interior 2x32 tile
    {
        const int pix = tid & 63;
        const int kh  = tid >> 6;
        const int gy  = y0 + (pix >> 5);
        const int gx  = x0 + (pix & 31);
        const float* xb = x + ((size_t)(b*256 + half*128 + kh*32)) * NPIX
                            + (size_t)gy*WW + gx;
        stage_a(As, xb, pix, kh);
    }

    float acc[2][4][4];

    // ---- k pass (weights at +16384) ----
    acc_zero(acc);
    #pragma unroll 1
    for (int c = 0; c < 2; ++c) {
        stage_b_chunk(Bc, qkv_w + 16384, c, tid);
        __syncthreads();
        mma_chunk4(acc, As, Bc, c*4, warp_m, warp_n, lane);
        __syncthreads();
    }
    write_kq_h(acc, Ks_h, warp_m, warp_n, lane);

    // ---- q pass (weights at +0) ----
    acc_zero(acc);
    #pragma unroll 1
    for (int c = 0; c < 2; ++c) {
        stage_b_chunk(Bc, qkv_w, c, tid);
        __syncthreads();
        mma_chunk4(acc, As, Bc, c*4, warp_m, warp_n, lane);
        __syncthreads();
    }
    write_kq_h(acc, Qs_h, warp_m, warp_n, lane);
    // A and B regions now dead (last sync was after final mma) -> vs overlay

    // stage vs_h[head(4)][4x34 halo][40 halves] fp16 from g_v
    for (int idx = tid; idx < 4*136*8; idx += 256) {
        int hh  = idx / 1088;
        int rem = idx - hh*1088;
        int pix = rem >> 3;
        int c8  = rem & 7;
        int py  = pix / 34;
        int px  = pix - py*34;
        int gy  = y0 - 1 + py;
        int gx  = x0 - 1 + px;
        float4 vv = make_float4(0.f, 0.f, 0.f, 0.f);
        if (gy >= 0 && gy < HH && gx >= 0 && gx < WW)
            vv = __ldg((const float4*)(g_v +
                    ((n4 + hh)*NPIX + (size_t)gy*WW + gx)*32) + c8);
        uint2 p;
        p.x = pkh2(vv.x, vv.y);
        p.y = pkh2(vv.z, vv.w);
        *(uint2*)(vs_h + (size_t)(hh*136 + pix)*40 + c8*4) = p;
    }
    __syncthreads();   // Ks/Qs/vs visible

    const float scale = 0.17677669529663687f;  // 1/sqrt(32)

    // ---- phase 1: logits + softmax -> aw  (256 thr = 4 heads x 16 win x 4 tok)
    {
        const int head = tid >> 6;
        const int t    = tid & 63;
        const int w    = t >> 2;
        const int i    = t & 3;
        const int sy   = i >> 1, sx = i & 1;
        const int lx   = 2*w + sx;

        uint32_t qh[16];
        {
            const uint4* qp = (const uint4*)(Qs_h + (size_t)(head*64 + sy*32 + lx)*40);
            #pragma unroll
            for (int r = 0; r < 4; ++r) *((uint4*)qh + r) = qp[r];
        }
        float lg[4];
        #pragma unroll
        for (int j = 0; j < 4; ++j) {
            const uint4* kp = (const uint4*)(Ks_h +
                (size_t)(head*64 + (j>>1)*32 + 2*w + (j&1))*40);
            float s = 0.f;
            #pragma unroll
            for (int r = 0; r < 4; ++r) {
                uint4 kk = kp[r];
                const uint32_t* kw = (const uint32_t*)&kk;
                #pragma unroll
                for (int u = 0; u < 4; ++u) {
                    float2 kf = __half22float2(*(const __half2*)&kw[u]);
                    float2 qf = __half22float2(*(const __half2*)&qh[r*4 + u]);
                    s = fmaf(qf.x, kf.x, s);
                    s = fmaf(qf.y, kf.y, s);
                }
            }
            lg[j] = s*scale + smf[SMF_BIAS + head*16 + i*4 + j];
        }
        float m  = fmaxf(fmaxf(lg[0], lg[1]), fmaxf(lg[2], lg[3]));
        float a0 = expf(lg[0] - m);
        float a1 = expf(lg[1] - m);
        float a2 = expf(lg[2] - m);
        float a3 = expf(lg[3] - m);
        float inv = 1.0f / (a0 + a1 + a2 + a3);
        *(float4*)(smf + SMF_AW + (size_t)(head*16 + w)*16 + i*4) =
            make_float4(a0*inv, a1*inv, a2*inv, a3*inv);
    }
    __syncthreads();

    // ---- phase 2: tap-grid walk (256 thr = 4 heads x 16 win x 4 chan-quads)
    {
        const int head = tid >> 6;
        const int rem  = tid & 63;
        const int w    = rem >> 2;
        const int cq   = rem & 3;

        // softmax weights for this window (shared across c8 iterations)
        float a[16];
        {
            const float* awp = smf + SMF_AW + (size_t)(head*16 + w)*16;
            #pragma unroll
            for (int r = 0; r < 4; ++r) *(float4*)(a + r*4) = *(const float4*)(awp + r*4);
        }
        const float* lwp = smf + SMF_LW + head*288;
        const float* lbp = smf + SMF_LB + head*32;
        const __half* vbase = vs_h + (size_t)head*136*40;

        #pragma unroll
        for (int c8i = 0; c8i < 2; ++c8i) {
            const int c8 = cq*2 + c8i;

            float4 wv[9];
            #pragma unroll
            for (int tp = 0; tp < 9; ++tp)
                wv[tp] = *(const float4*)(lwp + tp*32 + c8*4);
            float4 bb = *(const float4*)(lbp + c8*4);

            float accp[4][4];
            #pragma unroll
            for (int i = 0; i < 4; ++i) {
                accp[i][0] = bb.x; accp[i][1] = bb.y;
                accp[i][2] = bb.z; accp[i][3] = bb.w;
            }

            // 4x4 tap grid: halo rows 0..3, halo cols 2w..2w+3
            #pragma unroll
            for (int ty = 0; ty < 4; ++ty) {
                #pragma unroll
                for (int tx = 0; tx < 4; ++tx) {
                    const uint2 pv = *(const uint2*)(vbase +
                        (size_t)(ty*34 + 2*w + tx)*40 + c8*4);
                    float2 f01 = __half22float2(*(const __half2*)&pv.x);
                    float2 f23 = __half22float2(*(const __half2*)&pv.y);
                    float vvf[4] = {f01.x, f01.y, f23.x, f23.y};

                    // attention mix: tap is window token j?
                    if (ty >= 1 && ty <= 2 && tx >= 1 && tx <= 2) {
                        const int j = (ty - 1)*2 + (tx - 1);
                        #pragma unroll
                        for (int i = 0; i < 4; ++i) {
                            float aij = a[i*4 + j];
                            #pragma unroll
                            for (int e = 0; e < 4; ++e)
                                accp[i][e] = fmaf(aij, vvf[e], accp[i][e]);
                        }
                    }
                    // LePE: token i uses tap iff within its 3x3 stencil
                    #pragma unroll
                    for (int i = 0; i < 4; ++i) {
                        const int sy = i >> 1, sx = i & 1;
                        if (ty >= sy && ty <= sy + 2 && tx >= sx && tx <= sx + 2) {
                            const float* wp = (const float*)&wv[(ty - sy)*3 + (tx - sx)];
                            #pragma unroll
                            for (int e = 0; e < 4; ++e)
                                accp[i][e] = fmaf(wp[e], vvf[e], accp[i][e]);
                        }
                    }
                }
            }

            // stores
            #pragma unroll
            for (int i = 0; i < 4; ++i) {
                const int sy = i >> 1, sx = i & 1;
                const size_t ob = ((size_t)(b*256 + half*128 + head))*NPIX
                                + (size_t)(y0 + sy)*WW + (x0 + 2*w + sx);
                #pragma unroll
                for (int e = 0; e < 4; ++e)
                    out[ob + (size_t)(c8*4 + e)*4*NPIX] = accp[i][e];
            }
        }
    }
}

// ---------------------------------------------------------------------------
// Launcher
// ---------------------------------------------------------------------------
extern "C" void kernel_launch(void* const* d_in, const int* in_sizes, int n_in,
                              void* d_out, int out_size)
{
    const float* x          = (const float*)d_in[0];
    const float* qkv_w      = (const float*)d_in[1];
    const float* lepe_w     = (const float*)d_in[2];
    const float* lepe_b     = (const float*)d_in[3];
    const float* bias_table = (const float*)d_in[4];
    const int*   rel_idx    = (const int*)  d_in[5];
    float* out = (float*)d_out;

    cudaFuncSetAttribute(v_kernel, cudaFuncAttributeMaxDynamicSharedMemorySize, SM_TOT_V);
    cudaFuncSetAttribute(qkv_attn_kernel, cudaFuncAttributeMaxDynamicSharedMemorySize, SM_TOT_F);

    dim3 gv(NPIX/64, NB);            // 576 x 8
    v_kernel<<<gv, 256, SM_TOT_V>>>(x, qkv_w);

    dim3 gf(WW/32, HH/2, NB);        // 6 x 96 x 8
    qkv_attn_kernel<<<gf, 256, SM_TOT_F>>>(x, qkv_w, lepe_w, lepe_b,
                                           bias_table, rel_idx, out);
}

// round 12
// speedup vs baseline: 1.1461x; 1.1461x over previous
#include <cuda_runtime.h>
#include <cuda_fp16.h>
#include <cstdint>

// ---------------------------------------------------------------------------
// Problem constants
// ---------------------------------------------------------------------------
#define HH    192
#define WW    192
#define NPIX  (HH*WW)          // 36864
#define NB    8                // 2 halves * batch 4

// ---------------------------------------------------------------------------
// Device scratch: only v round-trips.
// ---------------------------------------------------------------------------
__device__ float g_v[8*4*NPIX*32];

// ---------------------------------------------------------------------------
// fp16 helpers (base-ISA mma.sync m16n8k16)
// ---------------------------------------------------------------------------
__device__ __forceinline__ uint32_t pkh2(float a, float b) {
    __half2 h = __floats2half2_rn(a, b);   // low half = a
    return *reinterpret_cast<uint32_t*>(&h);
}
__device__ __forceinline__ void mma_f16(float* c, const uint4& a, const uint2& b) {
    asm volatile(
        "mma.sync.aligned.m16n8k16.row.col.f32.f16.f16.f32 "
        "{%0,%1,%2,%3}, {%4,%5,%6,%7}, {%8,%9}, {%0,%1,%2,%3};"
        : "+f"(c[0]), "+f"(c[1]), "+f"(c[2]), "+f"(c[3])
        : "r"(a.x), "r"(a.y), "r"(a.z), "r"(a.w), "r"(b.x), "r"(b.y));
}

#define B_KSTRIDE 1026   // b32 per kstep block

// ---- fused-kernel smem map (float units) ------------------------------------
// [0 .. 4096)        A tile (64 pix x 128 k fp16 frags)
// [4096 .. 8200)     B chunk (4 ksteps)
//   vs_h overlay: [0, 4896) floats = 2 heads x (4x34 halo) x 36 halves
// [8200 .. 13320)    Ks_h: 4 heads x 64 pix x 40 halves
// [13320 .. 15880)   Qs_h: 2 heads x 64 pix x 40 halves (pair)
// [15880 .. 16392)   aw: softmax weights [hp(2)][win 16][tok 4][4] fp32
// [16392 .. 16968)   lw_h: lepe weights fp16 [head][tap][hd]
// [16968 .. 17096)   lepe bias fp32 [head][hd]
// [17096 .. 17160)   attn bias fp32 [head][i*4+j]
#define SMF_B    4096
#define SMF_KH   8200
#define SMF_QH   13320
#define SMF_AW   15880
#define SMF_LWH  16392
#define SMF_LB   16968
#define SMF_BIAS 17096
#define SM_TOT_F (17160*4)     // 68640 B -> 3 CTAs/SM

// ---- v-kernel smem map -------------------------------------------------------
#define SMF_VB  4096
#define SMF_VC  8200
#define SM_TOT_V (17416*4)     // 69664 B -> 3 CTAs/SM

// ---------------------------------------------------------------------------
// B chunk staging (256 threads): weights [o(128)][k(128)] fp32 -> fp16 frag
// ---------------------------------------------------------------------------
__device__ __forceinline__ void stage_b_chunk(uint32_t* __restrict__ Bc,
                                              const float* __restrict__ w,
                                              int c, int tid)
{
    #pragma unroll
    for (int it = 0; it < 8; ++it) {
        int i   = it*256 + tid;      // 0..2047
        int o   = i >> 4;            // 0..127
        int k4l = i & 15;
        float4 v = __ldg((const float4*)(w + (size_t)o*128) + (c*16 + k4l));
        int ksl = k4l >> 2;
        int kc  = (k4l & 3) * 4;
        int tg0 = (kc >> 1) & 3;
        int r   = kc >> 3;
        uint32_t base = (uint32_t)(ksl*B_KSTRIDE + (o>>3)*64 + ((o&7)*4 + tg0)*2 + r);
        Bc[base    ] = pkh2(v.x, v.y);
        Bc[base + 2] = pkh2(v.z, v.w);
    }
}

// ---------------------------------------------------------------------------
// MMA over one 4-kstep chunk; 8 warps: warp tile 32(M) x 32(N), M total 64
// ---------------------------------------------------------------------------
__device__ __forceinline__ void mma_chunk4(float acc[2][4][4],
                                           const uint32_t* __restrict__ As,
                                           const uint32_t* __restrict__ Bc,
                                           int ks0, int warp_m, int warp_n, int lane)
{
    #pragma unroll
    for (int l = 0; l < 4; ++l) {
        const int kg = ks0 + l;
        uint4 a[2];
        #pragma unroll
        for (int i = 0; i < 2; ++i) {
            uint32_t u = (uint32_t)((kg*4 + warp_m*2 + i)*32 + lane);
            u ^= (u >> 3) & 7;
            a[i] = *(const uint4*)(As + (size_t)u*4);
        }
        uint2 bf[4];
        #pragma unroll
        for (int j = 0; j < 4; ++j)
            bf[j] = *(const uint2*)(Bc + l*B_KSTRIDE + (warp_n*4 + j)*64 + lane*2);
        #pragma unroll
        for (int i = 0; i < 2; ++i)
            #pragma unroll
            for (int j = 0; j < 4; ++j)
                mma_f16(acc[i][j], a[i], bf[j]);
    }
}

__device__ __forceinline__ void acc_zero(float acc[2][4][4]) {
    #pragma unroll
    for (int i = 0; i < 2; ++i)
        #pragma unroll
        for (int j = 0; j < 4; ++j)
            #pragma unroll
            for (int e = 0; e < 4; ++e) acc[i][j][e] = 0.0f;
}

// acc -> Cs fp32 [head(4)][pix 64][36]   (v_kernel epilogue)
__device__ __forceinline__ void write_c_all(const float acc[2][4][4],
                                            float* __restrict__ Cs,
                                            int warp_m, int warp_n, int lane)
{
    const int g  = lane >> 2;
    const int tg = lane & 3;
    #pragma unroll
    for (int i = 0; i < 2; ++i) {
        int pl = warp_m*32 + i*16 + g;
        #pragma unroll
        for (int j = 0; j < 4; ++j) {
            int o0 = warp_n*32 + j*8 + 2*tg;
            int h0 = o0 & 3, h1 = (o0 + 1) & 3;
            int hd = o0 >> 2;
            Cs[(h0*64 + pl    )*36 + hd] = acc[i][j][0];
            Cs[(h1*64 + pl    )*36 + hd] = acc[i][j][1];
            Cs[(h0*64 + pl + 8)*36 + hd] = acc[i][j][2];
            Cs[(h1*64 + pl + 8)*36 + hd] = acc[i][j][3];
        }
    }
}

// acc -> fp16 [head(4)][pix 64][stride 40]  (Ks_h)
__device__ __forceinline__ void write_k_h(const float acc[2][4][4],
                                          __half* __restrict__ K,
                                          int warp_m, int warp_n, int lane)
{
    const int g  = lane >> 2;
    const int tg = lane & 3;
    #pragma unroll
    for (int i = 0; i < 2; ++i) {
        int pl = warp_m*32 + i*16 + g;
        #pragma unroll
        for (int j = 0; j < 4; ++j) {
            int o0 = warp_n*32 + j*8 + 2*tg;
            int h0 = o0 & 3, h1 = (o0 + 1) & 3;
            int hd = o0 >> 2;
            K[(h0*64 + pl    )*40 + hd] = __float2half_rn(acc[i][j][0]);
            K[(h1*64 + pl    )*40 + hd] = __float2half_rn(acc[i][j][1]);
            K[(h0*64 + pl + 8)*40 + hd] = __float2half_rn(acc[i][j][2]);
            K[(h1*64 + pl + 8)*40 + hd] = __float2half_rn(acc[i][j][3]);
        }
    }
}

// acc -> Qs_h fp16 [hh(2)][pix 64][40] for one head-pair
__device__ __forceinline__ void write_q_h(const float acc[2][4][4],
                                          __half* __restrict__ Q, int pair,
                                          int warp_m, int warp_n, int lane)
{
    const int g  = lane >> 2;
    const int tg = lane & 3;
    if ((tg & 1) != pair) return;
    #pragma unroll
    for (int i = 0; i < 2; ++i) {
        int pl = warp_m*32 + i*16 + g;
        #pragma unroll
        for (int j = 0; j < 4; ++j) {
            int o0 = warp_n*32 + j*8 + 2*tg;
            int hd = o0 >> 2;
            Q[(0*64 + pl    )*40 + hd] = __float2half_rn(acc[i][j][0]);
            Q[(1*64 + pl    )*40 + hd] = __float2half_rn(acc[i][j][1]);
            Q[(0*64 + pl + 8)*40 + hd] = __float2half_rn(acc[i][j][2]);
            Q[(1*64 + pl + 8)*40 + hd] = __float2half_rn(acc[i][j][3]);
        }
    }
}

// ---------------------------------------------------------------------------
// A staging: 64 pixels x 128 k -> fp16 fragment-major + swizzle.
// ---------------------------------------------------------------------------
__device__ __forceinline__ void stage_a(uint32_t* __restrict__ As,
                                        const float* __restrict__ xb,
                                        int pix, int kh)
{
    const int mtile   = pix >> 4;
    const int g       = pix & 7;
    const int rowhalf = (pix >> 3) & 1;
    #pragma unroll 4
    for (int k2 = 0; k2 < 32; k2 += 2) {
        int k = kh*32 + k2;
        float f0 = __ldg(xb + (size_t)k2 * NPIX);
        float f1 = __ldg(xb + (size_t)(k2+1) * NPIX);
        int kstep = k >> 4;
        int kc    = k & 15;
        int colhalf = kc >> 3;
        int tg      = (kc >> 1) & 3;
        uint32_t u = (uint32_t)((kstep*4 + mtile)*32 + g*4 + tg);
        u ^= (u >> 3) & 7;
        As[u*4 + colhalf*2 + rowhalf] = pkh2(f0, f1);
    }
}

// ---------------------------------------------------------------------------
// Kernel 1: v = 1x1 conv (fp16 GEMM), M=64 linear blocks, 3 CTAs/SM
// ---------------------------------------------------------------------------
__global__ void __launch_bounds__(256, 3)
v_kernel(const float* __restrict__ x, const float* __restrict__ qkv_w)
{
    extern __shared__ __align__(16) float smf[];
    uint32_t* As = (uint32_t*)smf;
    uint32_t* Bc = (uint32_t*)(smf + SMF_VB);
    float*    Cs = smf + SMF_VC;

    const int tid    = threadIdx.x;
    const int lane   = tid & 31;
    const int wid    = tid >> 5;
    const int warp_m = wid >> 2;
    const int warp_n = wid & 3;
    const int n      = blockIdx.y;
    const int half   = n >> 2;
    const int b      = n & 3;
    const int p0     = blockIdx.x * 64;
    const size_t n4  = (size_t)n * 4;

    {
        const int pix = tid & 63;
        const int kh  = tid >> 6;
        const float* xb = x + ((size_t)(b*256 + half*128 + kh*32)) * NPIX + p0 + pix;
        stage_a(As, xb, pix, kh);
    }

    float acc[2][4][4];
    acc_zero(acc);
    #pragma unroll 1
    for (int c = 0; c < 2; ++c) {
        stage_b_chunk(Bc, qkv_w + 32768, c, tid);
        __syncthreads();
        mma_chunk4(acc, As, Bc, c*4, warp_m, warp_n, lane);
        __syncthreads();
    }

    write_c_all(acc, Cs, warp_m, warp_n, lane);
    __syncthreads();

    {
        int h   = tid >> 6;
        int pix = tid & 63;
        const float4* src = (const float4*)(Cs + (size_t)(h*64 + pix)*36);
        float4* d = (float4*)(g_v + ((n4 + h)*NPIX + (size_t)(p0 + pix))*32);
        #pragma unroll
        for (int c = 0; c < 8; ++c) d[c] = src[c];
    }
}

// ---------------------------------------------------------------------------
// Kernel 2: fused q,k GEMM + pair-looped split-phase attention + LePE.
// CTA = 2 rows x 32 cols, 256 threads, 3 CTAs/SM.
// ---------------------------------------------------------------------------
__global__ void __launch_bounds__(256, 3)
qkv_attn_kernel(const float* __restrict__ x, const float* __restrict__ qkv_w,
                const float* __restrict__ lepe_w, const float* __restrict__ lepe_b,
                const float* __restrict__ bias_table, const int* __restrict__ rel_idx,
                float* __restrict__ out)
{
    extern __shared__ __align__(16) float smf[];
    uint32_t* As   = (uint32_t*)smf;
    uint32_t* Bc   = (uint32_t*)(smf + SMF_B);
    __half*   vs_h = (__half*)smf;                // overlays A(+B) after GEMMs
    __half*   Ks_h = (__half*)(smf + SMF_KH);
    __half*   Qs_h = (__half*)(smf + SMF_QH);
    __half*   lw_h = (__half*)(smf + SMF_LWH);

    const int tid    = threadIdx.x;
    const int lane   = tid & 31;
    const int wid    = tid >> 5;
    const int warp_m = wid >> 2;
    const int warp_n = wid & 3;
    const int n      = blockIdx.z;
    const int half   = n >> 2;
    const int b      = n & 3;
    const int x0     = blockIdx.x * 32;
    const int y0     = blockIdx.y * 2;
    const size_t n4  = (size_t)n * 4;

    // stage per-head constants from raw inputs (tiny, L2-resident)
    for (int idx = tid; idx < 1152; idx += 256) {
        int head = idx / 288;
        int r    = idx % 288;
        int tap  = r >> 5;
        int hd   = r & 31;
        lw_h[idx] = __float2half_rn(__ldg(&lepe_w[(hd*4 + head)*9 + tap]));
    }
    if (tid < 128) {
        smf[SMF_LB + tid] = __ldg(&lepe_b[(tid & 31)*4 + (tid >> 5)]);
    } else if (tid < 192) {
        int t2 = tid - 128;
        int head = t2 >> 4, ij = t2 & 15;
        smf[SMF_BIAS + t2] = __ldg(&bias_table[__ldg(&rel_idx[ij])*4 + head]);
    }

    // stage A: interior 2x32 tile
    {
        const int pix = tid & 63;
        const int kh  = tid >> 6;
        const int gy  = y0 + (pix >> 5);
        const int gx  = x0 + (pix & 31);
        const float* xb = x + ((size_t)(b*256 + half*128 + kh*32)) * NPIX
                            + (size_t)gy*WW + gx;
        stage_a(As, xb, pix, kh);
    }

    float acck[2][4][4];

    // ---- k pass (weights at +16384) ----
    acc_zero(acck);
    #pragma unroll 1
    for (int c = 0; c < 2; ++c) {
        stage_b_chunk(Bc, qkv_w + 16384, c, tid);
        __syncthreads();
        mma_chunk4(acck, As, Bc, c*4, warp_m, warp_n, lane);
        __syncthreads();
    }
    write_k_h(acck, Ks_h, warp_m, warp_n, lane);

    // ---- q pass (weights at +0); acc lives across the pair loop ----
    float acc[2][4][4];
    acc_zero(acc);
    #pragma unroll 1
    for (int c = 0; c < 2; ++c) {
        stage_b_chunk(Bc, qkv_w, c, tid);
        __syncthreads();
        mma_chunk4(acc, As, Bc, c*4, warp_m, warp_n, lane);
        __syncthreads();
    }
    // A and B regions now dead -> vs overlay allowed

    const float scale = 0.17677669529663687f;  // 1/sqrt(32)

    #pragma unroll 1
    for (int pair = 0; pair < 2; ++pair) {
        // park this pair's q (fp16)
        write_q_h(acc, Qs_h, pair, warp_m, warp_n, lane);

        // stage vs_h[hh(2)][4x34 halo][36 halves] fp16 from g_v
        for (int idx = tid; idx < 2*136*8; idx += 256) {
            int hh  = idx / 1088;
            int rem = idx - hh*1088;
            int pix = rem >> 3;
            int c8  = rem & 7;
            int py  = pix / 34;
            int px  = pix - py*34;
            int gy  = y0 - 1 + py;
            int gx  = x0 - 1 + px;
            float4 vv = make_float4(0.f, 0.f, 0.f, 0.f);
            if (gy >= 0 && gy < HH && gx >= 0 && gx < WW)
                vv = __ldg((const float4*)(g_v +
                        ((n4 + pair*2 + hh)*NPIX + (size_t)gy*WW + gx)*32) + c8);
            uint2 p;
            p.x = pkh2(vv.x, vv.y);
            p.y = pkh2(vv.z, vv.w);
            *(uint2*)(vs_h + (size_t)(hh*136 + pix)*36 + c8*4) = p;
        }
        __syncthreads();   // Qs/vs visible

        // ---- phase 1: logits + softmax (128 thr = 2 heads x 16 win x 4 tok)
        if (tid < 128) {
            const int hp   = tid >> 6;
            const int t    = tid & 63;
            const int w    = t >> 2;
            const int i    = t & 3;
            const int head = pair*2 + hp;
            const int sy   = i >> 1, sx = i & 1;
            const int lx   = 2*w + sx;

            uint32_t qh[16];
            {
                const uint4* qp = (const uint4*)(Qs_h + (size_t)(hp*64 + sy*32 + lx)*40);
                #pragma unroll
                for (int r = 0; r < 4; ++r) *((uint4*)qh + r) = qp[r];
            }
            float lg[4];
            #pragma unroll
            for (int j = 0; j < 4; ++j) {
                const uint4* kp = (const uint4*)(Ks_h +
                    (size_t)(head*64 + (j>>1)*32 + 2*w + (j&1))*40);
                float s = 0.f;
                #pragma unroll
                for (int r = 0; r < 4; ++r) {
                    uint4 kk = kp[r];
                    const uint32_t* kw = (const uint32_t*)&kk;
                    #pragma unroll
                    for (int u = 0; u < 4; ++u) {
                        float2 kf = __half22float2(*(const __half2*)&kw[u]);
                        float2 qf = __half22float2(*(const __half2*)&qh[r*4 + u]);
                        s = fmaf(qf.x, kf.x, s);
                        s = fmaf(qf.y, kf.y, s);
                    }
                }
                lg[j] = s*scale + smf[SMF_BIAS + head*16 + i*4 + j];
            }
            float m  = fmaxf(fmaxf(lg[0], lg[1]), fmaxf(lg[2], lg[3]));
            float a0 = expf(lg[0] - m);
            float a1 = expf(lg[1] - m);
            float a2 = expf(lg[2] - m);
            float a3 = expf(lg[3] - m);
            float inv = 1.0f / (a0 + a1 + a2 + a3);
            *(float4*)(smf + SMF_AW + (size_t)(hp*16 + w)*16 + i*4) =
                make_float4(a0*inv, a1*inv, a2*inv, a3*inv);
        }
        __syncthreads();

        // ---- phase 2: tap-grid walk (256 thr = 2 heads x 16 win x 8 c8)
        {
            const int hp   = tid >> 7;
            const int rem  = tid & 127;
            const int w    = rem >> 3;
            const int c8   = rem & 7;
            const int head = pair*2 + hp;

            float a[16];
            {
                const float* awp = smf + SMF_AW + (size_t)(hp*16 + w)*16;
                #pragma unroll
                for (int r = 0; r < 4; ++r)
                    *(float4*)(a + r*4) = *(const float4*)(awp + r*4);
            }
            uint2 wvh[9];
            {
                const __half* lwp = lw_h + head*288;
                #pragma unroll
                for (int tp = 0; tp < 9; ++tp)
                    wvh[tp] = *(const uint2*)(lwp + tp*32 + c8*4);
            }
            float4 bb = *(const float4*)(smf + SMF_LB + head*32 + c8*4);

            float accp[4][4];
            #pragma unroll
            for (int i = 0; i < 4; ++i) {
                accp[i][0] = bb.x; accp[i][1] = bb.y;
                accp[i][2] = bb.z; accp[i][3] = bb.w;
            }

            const __half* vbase = vs_h + (size_t)hp*136*36;

            #pragma unroll
            for (int ty = 0; ty < 4; ++ty) {
                #pragma unroll
                for (int tx = 0; tx < 4; ++tx) {
                    const uint2 pv = *(const uint2*)(vbase +
                        (size_t)(ty*34 + 2*w + tx)*36 + c8*4);
                    float2 f01 = __half22float2(*(const __half2*)&pv.x);
                    float2 f23 = __half22float2(*(const __half2*)&pv.y);
                    float vvf[4] = {f01.x, f01.y, f23.x, f23.y};

                    if (ty >= 1 && ty <= 2 && tx >= 1 && tx <= 2) {
                        const int j = (ty - 1)*2 + (tx - 1);
                        #pragma unroll
                        for (int i = 0; i < 4; ++i) {
                            float aij = a[i*4 + j];
                            #pragma unroll
                            for (int e = 0; e < 4; ++e)
                                accp[i][e] = fmaf(aij, vvf[e], accp[i][e]);
                        }
                    }
                    #pragma unroll
                    for (int i = 0; i < 4; ++i) {
                        const int sy = i >> 1, sx = i & 1;
                        if (ty >= sy && ty <= sy + 2 && tx >= sx && tx <= sx + 2) {
                            const uint2 wh = wvh[(ty - sy)*3 + (tx - sx)];
                            float2 w01 = __half22float2(*(const __half2*)&wh.x);
                            float2 w23 = __half22float2(*(const __half2*)&wh.y);
                            accp[i][0] = fmaf(w01.x, vvf[0], accp[i][0]);
                            accp[i][1] = fmaf(w01.y, vvf[1], accp[i][1]);
                            accp[i][2] = fmaf(w23.x, vvf[2], accp[i][2]);
                            accp[i][3] = fmaf(w23.y, vvf[3], accp[i][3]);
                        }
                    }
                }
            }

            #pragma unroll
            for (int i = 0; i < 4; ++i) {
                const int sy = i >> 1, sx = i & 1;
                const size_t ob = ((size_t)(b*256 + half*128 + head))*NPIX
                                + (size_t)(y0 + sy)*WW + (x0 + 2*w + sx);
                #pragma unroll
                for (int e = 0; e < 4; ++e)
                    out[ob + (size_t)(c8*4 + e)*4*NPIX] = accp[i][e];
            }
        }
        __syncthreads();   // pair reads done before Qs/vs/aw rewritten
    }
}

// ---------------------------------------------------------------------------
// Launcher
// ---------------------------------------------------------------------------
extern "C" void kernel_launch(void* const* d_in, const int* in_sizes, int n_in,
                              void* d_out, int out_size)
{
    const float* x          = (const float*)d_in[0];
    const float* qkv_w      = (const float*)d_in[1];
    const float* lepe_w     = (const float*)d_in[2];
    const float* lepe_b     = (const float*)d_in[3];
    const float* bias_table = (const float*)d_in[4];
    const int*   rel_idx    = (const int*)  d_in[5];
    float* out = (float*)d_out;

    cudaFuncSetAttribute(v_kernel, cudaFuncAttributeMaxDynamicSharedMemorySize, SM_TOT_V);
    cudaFuncSetAttribute(qkv_attn_kernel, cudaFuncAttributeMaxDynamicSharedMemorySize, SM_TOT_F);

    dim3 gv(NPIX/64, NB);            // 576 x 8
    v_kernel<<<gv, 256, SM_TOT_V>>>(x, qkv_w);

    dim3 gf(WW/32, HH/2, NB);        // 6 x 96 x 8
    qkv_attn_kernel<<<gf, 256, SM_TOT_F>>>(x, qkv_w, lepe_w, lepe_b,
                                           bias_table, rel_idx, out);
}

// round 14
// speedup vs baseline: 1.3083x; 1.1415x over previous
#include <cuda_runtime.h>
#include <cuda_fp16.h>
#include <cstdint>

// ---------------------------------------------------------------------------
// Problem constants
// ---------------------------------------------------------------------------
#define HH    192
#define WW    192
#define NPIX  (HH*WW)          // 36864
#define NB    8                // 2 halves * batch 4

// ---------------------------------------------------------------------------
// Device scratch: v round-trips in fp16 (rounding identical to prior vs_h path)
// layout: [n(8)][head(4)][pixel(36864)][hd(32)] halves
// ---------------------------------------------------------------------------
__device__ __half g_vh[8*4*NPIX*32];

// ---------------------------------------------------------------------------
// fp16 helpers (base-ISA mma.sync m16n8k16)
// ---------------------------------------------------------------------------
__device__ __forceinline__ uint32_t pkh2(float a, float b) {
    __half2 h = __floats2half2_rn(a, b);   // low half = a
    return *reinterpret_cast<uint32_t*>(&h);
}
__device__ __forceinline__ void mma_f16(float* c, const uint4& a, const uint2& b) {
    asm volatile(
        "mma.sync.aligned.m16n8k16.row.col.f32.f16.f16.f32 "
        "{%0,%1,%2,%3}, {%4,%5,%6,%7}, {%8,%9}, {%0,%1,%2,%3};"
        : "+f"(c[0]), "+f"(c[1]), "+f"(c[2]), "+f"(c[3])
        : "r"(a.x), "r"(a.y), "r"(a.z), "r"(a.w), "r"(b.x), "r"(b.y));
}

#define B_KSTRIDE 1026   // b32 per kstep block

// ---- fused-kernel smem map (float units) ------------------------------------
// [0 .. 4096)        A tile (64 pix x 128 k fp16 frags)
// [4096 .. 8200)     B chunk (4 ksteps)
//   vs_h overlay: [0, 4896) floats = 2 heads x (4x34 halo) x 36 halves
// [8200 .. 13320)    Ks_h: 4 heads x 64 pix x 40 halves
// [13320 .. 15880)   Qs_h: 2 heads x 64 pix x 40 halves (pair)
// [15880 .. 16392)   aw: softmax weights [hp(2)][win 16][tok 4][4] fp32
// [16392 .. 16968)   lw_h: lepe weights fp16 [head][tap][hd]
// [16968 .. 17096)   lepe bias fp32 [head][hd]
// [17096 .. 17160)   attn bias fp32 [head][i*4+j]
#define SMF_B    4096
#define SMF_KH   8200
#define SMF_QH   13320
#define SMF_AW   15880
#define SMF_LWH  16392
#define SMF_LB   16968
#define SMF_BIAS 17096
#define SM_TOT_F (17160*4)     // 68640 B -> 3 CTAs/SM

// ---- v-kernel smem map (float units) -----------------------------------------
// [0..4096) A   [4096..12304) B full (8 ksteps)
// [12304..17424) Cs_h (4 x 64 x 40 halves = 5120 floats)
#define SMF_VB  4096
#define SMF_VC  12304
#define SM_TOT_V (17424*4)     // 69696 B -> 3 CTAs/SM

// ---------------------------------------------------------------------------
// B chunk staging (256 threads): weights [o(128)][k(128)] fp32 -> fp16 frag
// ---------------------------------------------------------------------------
__device__ __forceinline__ void stage_b_chunk(uint32_t* __restrict__ Bc,
                                              const float* __restrict__ w,
                                              int c, int tid)
{
    #pragma unroll
    for (int it = 0; it < 8; ++it) {
        int i   = it*256 + tid;      // 0..2047
        int o   = i >> 4;            // 0..127
        int k4l = i & 15;
        float4 v = __ldg((const float4*)(w + (size_t)o*128) + (c*16 + k4l));
        int ksl = k4l >> 2;
        int kc  = (k4l & 3) * 4;
        int tg0 = (kc >> 1) & 3;
        int r   = kc >> 3;
        uint32_t base = (uint32_t)(ksl*B_KSTRIDE + (o>>3)*64 + ((o&7)*4 + tg0)*2 + r);
        Bc[base    ] = pkh2(v.x, v.y);
        Bc[base + 2] = pkh2(v.z, v.w);
    }
}

// ---------------------------------------------------------------------------
// MMA over one 4-kstep chunk; 8 warps: warp tile 32(M) x 32(N), M total 64
// ---------------------------------------------------------------------------
__device__ __forceinline__ void mma_chunk4(float acc[2][4][4],
                                           const uint32_t* __restrict__ As,
                                           const uint32_t* __restrict__ Bc,
                                           int ks0, int warp_m, int warp_n, int lane)
{
    #pragma unroll
    for (int l = 0; l < 4; ++l) {
        const int kg = ks0 + l;
        uint4 a[2];
        #pragma unroll
        for (int i = 0; i < 2; ++i) {
            uint32_t u = (uint32_t)((kg*4 + warp_m*2 + i)*32 + lane);
            u ^= (u >> 3) & 7;
            a[i] = *(const uint4*)(As + (size_t)u*4);
        }
        uint2 bf[4];
        #pragma unroll
        for (int j = 0; j < 4; ++j)
            bf[j] = *(const uint2*)(Bc + l*B_KSTRIDE + (warp_n*4 + j)*64 + lane*2);
        #pragma unroll
        for (int i = 0; i < 2; ++i)
            #pragma unroll
            for (int j = 0; j < 4; ++j)
                mma_f16(acc[i][j], a[i], bf[j]);
    }
}

__device__ __forceinline__ void acc_zero(float acc[2][4][4]) {
    #pragma unroll
    for (int i = 0; i < 2; ++i)
        #pragma unroll
        for (int j = 0; j < 4; ++j)
            #pragma unroll
            for (int e = 0; e < 4; ++e) acc[i][j][e] = 0.0f;
}

// acc -> fp16 [head(4)][pix 64][stride 40]  (Ks_h / v-kernel Cs_h)
__device__ __forceinline__ void write_kc_h(const float acc[2][4][4],
                                           __half* __restrict__ K,
                                           int warp_m, int warp_n, int lane)
{
    const int g  = lane >> 2;
    const int tg = lane & 3;
    #pragma unroll
    for (int i = 0; i < 2; ++i) {
        int pl = warp_m*32 + i*16 + g;
        #pragma unroll
        for (int j = 0; j < 4; ++j) {
            int o0 = warp_n*32 + j*8 + 2*tg;
            int h0 = o0 & 3, h1 = (o0 + 1) & 3;
            int hd = o0 >> 2;
            K[(h0*64 + pl    )*40 + hd] = __float2half_rn(acc[i][j][0]);
            K[(h1*64 + pl    )*40 + hd] = __float2half_rn(acc[i][j][1]);
            K[(h0*64 + pl + 8)*40 + hd] = __float2half_rn(acc[i][j][2]);
            K[(h1*64 + pl + 8)*40 + hd] = __float2half_rn(acc[i][j][3]);
        }
    }
}

// acc -> Qs_h fp16 [hh(2)][pix 64][40] for one head-pair
__device__ __forceinline__ void write_q_h(const float acc[2][4][4],
                                          __half* __restrict__ Q, int pair,
                                          int warp_m, int warp_n, int lane)
{
    const int g  = lane >> 2;
    const int tg = lane & 3;
    if ((tg & 1) != pair) return;
    #pragma unroll
    for (int i = 0; i < 2; ++i) {
        int pl = warp_m*32 + i*16 + g;
        #pragma unroll
        for (int j = 0; j < 4; ++j) {
            int o0 = warp_n*32 + j*8 + 2*tg;
            int hd = o0 >> 2;
            Q[(0*64 + pl    )*40 + hd] = __float2half_rn(acc[i][j][0]);
            Q[(1*64 + pl    )*40 + hd] = __float2half_rn(acc[i][j][1]);
            Q[(0*64 + pl + 8)*40 + hd] = __float2half_rn(acc[i][j][2]);
            Q[(1*64 + pl + 8)*40 + hd] = __float2half_rn(acc[i][j][3]);
        }
    }
}

// ---------------------------------------------------------------------------
// A staging: 64 pixels x 128 k -> fp16 fragment-major + swizzle.
// ---------------------------------------------------------------------------
__device__ __forceinline__ void stage_a(uint32_t* __restrict__ As,
                                        const float* __restrict__ xb,
                                        int pix, int kh)
{
    const int mtile   = pix >> 4;
    const int g       = pix & 7;
    const int rowhalf = (pix >> 3) & 1;
    #pragma unroll 4
    for (int k2 = 0; k2 < 32; k2 += 2) {
        int k = kh*32 + k2;
        float f0 = __ldg(xb + (size_t)k2 * NPIX);
        float f1 = __ldg(xb + (size_t)(k2+1) * NPIX);
        int kstep = k >> 4;
        int kc    = k & 15;
        int colhalf = kc >> 3;
        int tg      = (kc >> 1) & 3;
        uint32_t u = (uint32_t)((kstep*4 + mtile)*32 + g*4 + tg);
        u ^= (u >> 3) & 7;
        As[u*4 + colhalf*2 + rowhalf] = pkh2(f0, f1);
    }
}

// ---------------------------------------------------------------------------
// Kernel 1: v = 1x1 conv (fp16 GEMM), M=64 linear blocks, 3 CTAs/SM.
// Single-shot B staging; fp16 epilogue straight to g_vh.
// ---------------------------------------------------------------------------
__global__ void __launch_bounds__(256, 3)
v_kernel(const float* __restrict__ x, const float* __restrict__ qkv_w)
{
    extern __shared__ __align__(16) float smf[];
    uint32_t* As   = (uint32_t*)smf;
    uint32_t* Bf   = (uint32_t*)(smf + SMF_VB);
    __half*   Cs_h = (__half*)(smf + SMF_VC);

    const int tid    = threadIdx.x;
    const int lane   = tid & 31;
    const int wid    = tid >> 5;
    const int warp_m = wid >> 2;
    const int warp_n = wid & 3;
    const int n      = blockIdx.y;
    const int half_  = n >> 2;
    const int b      = n & 3;
    const int p0     = blockIdx.x * 64;
    const size_t n4  = (size_t)n * 4;

    {
        const int pix = tid & 63;
        const int kh  = tid >> 6;
        const float* xb = x + ((size_t)(b*256 + half_*128 + kh*32)) * NPIX + p0 + pix;
        stage_a(As, xb, pix, kh);
    }
    // stage full B (v weights, 8 ksteps) in one shot
    stage_b_chunk(Bf,               qkv_w + 32768, 0, tid);
    stage_b_chunk(Bf + 4*B_KSTRIDE, qkv_w + 32768, 1, tid);
    __syncthreads();

    float acc[2][4][4];
    acc_zero(acc);
    mma_chunk4(acc, As, Bf,               0, warp_m, warp_n, lane);
    mma_chunk4(acc, As, Bf + 4*B_KSTRIDE, 4, warp_m, warp_n, lane);

    write_kc_h(acc, Cs_h, warp_m, warp_n, lane);
    __syncthreads();

    // drain: one (head,pixel) row per thread, 4 x STG.128 (64B fp16) linear
    {
        int h   = tid >> 6;
        int pix = tid & 63;
        const uint4* src = (const uint4*)(Cs_h + (size_t)(h*64 + pix)*40);
        uint4* d = (uint4*)(g_vh + ((n4 + h)*NPIX + (size_t)(p0 + pix))*32);
        #pragma unroll
        for (int c = 0; c < 4; ++c) d[c] = src[c];
    }
}

// ---------------------------------------------------------------------------
// Kernel 2: fused q,k GEMM + pair-looped split-phase attention + LePE.
// CTA = 2 rows x 32 cols, 256 threads, 3 CTAs/SM.
// ---------------------------------------------------------------------------
__global__ void __launch_bounds__(256, 3)
qkv_attn_kernel(const float* __restrict__ x, const float* __restrict__ qkv_w,
                const float* __restrict__ lepe_w, const float* __restrict__ lepe_b,
                const float* __restrict__ bias_table, const int* __restrict__ rel_idx,
                float* __restrict__ out)
{
    extern __shared__ __align__(16) float smf[];
    uint32_t* As   = (uint32_t*)smf;
    uint32_t* Bc   = (uint32_t*)(smf + SMF_B);
    __half*   vs_h = (__half*)smf;                // overlays A(+B) after GEMMs
    __half*   Ks_h = (__half*)(smf + SMF_KH);
    __half*   Qs_h = (__half*)(smf + SMF_QH);
    __half*   lw_h = (__half*)(smf + SMF_LWH);

    const int tid    = threadIdx.x;
    const int lane   = tid & 31;
    const int wid    = tid >> 5;
    const int warp_m = wid >> 2;
    const int warp_n = wid & 3;
    const int n      = blockIdx.z;
    const int half_  = n >> 2;
    const int b      = n & 3;
    const int x0     = blockIdx.x * 32;
    const int y0     = blockIdx.y * 2;
    const size_t n4  = (size_t)n * 4;

    // stage per-head constants from raw inputs (tiny, L2-resident)
    for (int idx = tid; idx < 1152; idx += 256) {
        int head = idx / 288;
        int r    = idx % 288;
        int tap  = r >> 5;
        int hd   = r & 31;
        lw_h[idx] = __float2half_rn(__ldg(&lepe_w[(hd*4 + head)*9 + tap]));
    }
    if (tid < 128) {
        smf[SMF_LB + tid] = __ldg(&lepe_b[(tid & 31)*4 + (tid >> 5)]);
    } else if (tid < 192) {
        int t2 = tid - 128;
        int head = t2 >> 4, ij = t2 & 15;
        smf[SMF_BIAS + t2] = __ldg(&bias_table[__ldg(&rel_idx[ij])*4 + head]);
    }

    // stage A: interior 2x32 tile
    {
        const int pix = tid & 63;
        const int kh  = tid >> 6;
        const int gy  = y0 + (pix >> 5);
        const int gx  = x0 + (pix & 31);
        const float* xb = x + ((size_t)(b*256 + half_*128 + kh*32)) * NPIX
                            + (size_t)gy*WW + gx;
        stage_a(As, xb, pix, kh);
    }

    float acck[2][4][4];

    // ---- k pass (weights at +16384) ----
    acc_zero(acck);
    #pragma unroll 1
    for (int c = 0; c < 2; ++c) {
        stage_b_chunk(Bc, qkv_w + 16384, c, tid);
        __syncthreads();
        mma_chunk4(acck, As, Bc, c*4, warp_m, warp_n, lane);
        __syncthreads();
    }
    write_kc_h(acck, Ks_h, warp_m, warp_n, lane);

    // ---- q pass (weights at +0); acc lives across the pair loop ----
    float acc[2][4][4];
    acc_zero(acc);
    #pragma unroll 1
    for (int c = 0; c < 2; ++c) {
        stage_b_chunk(Bc, qkv_w, c, tid);
        __syncthreads();
        mma_chunk4(acc, As, Bc, c*4, warp_m, warp_n, lane);
        __syncthreads();
    }
    // A and B regions now dead -> vs overlay allowed

    const float scale = 0.17677669529663687f;  // 1/sqrt(32)

    #pragma unroll 1
    for (int pair = 0; pair < 2; ++pair) {
        // park this pair's q (fp16)
        write_q_h(acc, Qs_h, pair, warp_m, warp_n, lane);

        // stage vs_h[hh(2)][4x34 halo][36 halves] straight from fp16 g_vh
        for (int idx = tid; idx < 2*136*8; idx += 256) {
            int hh  = idx / 1088;
            int rem = idx - hh*1088;
            int pix = rem >> 3;
            int c8  = rem & 7;
            int py  = pix / 34;
            int px  = pix - py*34;
            int gy  = y0 - 1 + py;
            int gx  = x0 - 1 + px;
            uint2 p = make_uint2(0u, 0u);
            if (gy >= 0 && gy < HH && gx >= 0 && gx < WW)
                p = *(const uint2*)(g_vh +
                        ((n4 + pair*2 + hh)*NPIX + (size_t)gy*WW + gx)*32 + c8*4);
            *(uint2*)(vs_h + (size_t)(hh*136 + pix)*36 + c8*4) = p;
        }
        __syncthreads();   // Qs/vs visible

        // ---- phase 1: logits + softmax (128 thr = 2 heads x 16 win x 4 tok)
        if (tid < 128) {
            const int hp   = tid >> 6;
            const int t    = tid & 63;
            const int w    = t >> 2;
            const int i    = t & 3;
            const int head = pair*2 + hp;
            const int sy   = i >> 1, sx = i & 1;
            const int lx   = 2*w + sx;

            uint32_t qh[16];
            {
                const uint4* qp = (const uint4*)(Qs_h + (size_t)(hp*64 + sy*32 + lx)*40);
                #pragma unroll
                for (int r = 0; r < 4; ++r) *((uint4*)qh + r) = qp[r];
            }
            float lg[4];
            #pragma unroll
            for (int j = 0; j < 4; ++j) {
                const uint4* kp = (const uint4*)(Ks_h +
                    (size_t)(head*64 + (j>>1)*32 + 2*w + (j&1))*40);
                float s = 0.f;
                #pragma unroll
                for (int r = 0; r < 4; ++r) {
                    uint4 kk = kp[r];
                    const uint32_t* kw = (const uint32_t*)&kk;
                    #pragma unroll
                    for (int u = 0; u < 4; ++u) {
                        float2 kf = __half22float2(*(const __half2*)&kw[u]);
                        float2 qf = __half22float2(*(const __half2*)&qh[r*4 + u]);
                        s = fmaf(qf.x, kf.x, s);
                        s = fmaf(qf.y, kf.y, s);
                    }
                }
                lg[j] = s*scale + smf[SMF_BIAS + head*16 + i*4 + j];
            }
            float m  = fmaxf(fmaxf(lg[0], lg[1]), fmaxf(lg[2], lg[3]));
            float a0 = expf(lg[0] - m);
            float a1 = expf(lg[1] - m);
            float a2 = expf(lg[2] - m);
            float a3 = expf(lg[3] - m);
            float inv = 1.0f / (a0 + a1 + a2 + a3);
            *(float4*)(smf + SMF_AW + (size_t)(hp*16 + w)*16 + i*4) =
                make_float4(a0*inv, a1*inv, a2*inv, a3*inv);
        }
        __syncthreads();

        // ---- phase 2: tap-grid walk (256 thr = 2 heads x 16 win x 8 c8)
        {
            const int hp   = tid >> 7;
            const int rem  = tid & 127;
            const int w    = rem >> 3;
            const int c8   = rem & 7;
            const int head = pair*2 + hp;

            float a[16];
            {
                const float* awp = smf + SMF_AW + (size_t)(hp*16 + w)*16;
                #pragma unroll
                for (int r = 0; r < 4; ++r)
                    *(float4*)(a + r*4) = *(const float4*)(awp + r*4);
            }
            uint2 wvh[9];
            {
                const __half* lwp = lw_h + head*288;
                #pragma unroll
                for (int tp = 0; tp < 9; ++tp)
                    wvh[tp] = *(const uint2*)(lwp + tp*32 + c8*4);
            }
            float4 bb = *(const float4*)(smf + SMF_LB + head*32 + c8*4);

            float accp[4][4];
            #pragma unroll
            for (int i = 0; i < 4; ++i) {
                accp[i][0] = bb.x; accp[i][1] = bb.y;
                accp[i][2] = bb.z; accp[i][3] = bb.w;
            }

            const __half* vbase = vs_h + (size_t)hp*136*36;

            #pragma unroll
            for (int ty = 0; ty < 4; ++ty) {
                #pragma unroll
                for (int tx = 0; tx < 4; ++tx) {
                    const uint2 pv = *(const uint2*)(vbase +
                        (size_t)(ty*34 + 2*w + tx)*36 + c8*4);
                    float2 f01 = __half22float2(*(const __half2*)&pv.x);
                    float2 f23 = __half22float2(*(const __half2*)&pv.y);
                    float vvf[4] = {f01.x, f01.y, f23.x, f23.y};

                    if (ty >= 1 && ty <= 2 && tx >= 1 && tx <= 2) {
                        const int j = (ty - 1)*2 + (tx - 1);
                        #pragma unroll
                        for (int i = 0; i < 4; ++i) {
                            float aij = a[i*4 + j];
                            #pragma unroll
                            for (int e = 0; e < 4; ++e)
                                accp[i][e] = fmaf(aij, vvf[e], accp[i][e]);
                        }
                    }
                    #pragma unroll
                    for (int i = 0; i < 4; ++i) {
                        const int sy = i >> 1, sx = i & 1;
                        if (ty >= sy && ty <= sy + 2 && tx >= sx && tx <= sx + 2) {
                            const uint2 wh = wvh[(ty - sy)*3 + (tx - sx)];
                            float2 w01 = __half22float2(*(const __half2*)&wh.x);
                            float2 w23 = __half22float2(*(const __half2*)&wh.y);
                            accp[i][0] = fmaf(w01.x, vvf[0], accp[i][0]);
                            accp[i][1] = fmaf(w01.y, vvf[1], accp[i][1]);
                            accp[i][2] = fmaf(w23.x, vvf[2], accp[i][2]);
                            accp[i][3] = fmaf(w23.y, vvf[3], accp[i][3]);
                        }
                    }
                }
            }

            // packed float2 stores: (sx=0, sx=1) pair per row -> STG.64
            #pragma unroll
            for (int syi = 0; syi < 2; ++syi) {
                const size_t obr = ((size_t)(b*256 + half_*128 + head))*NPIX
                                 + (size_t)(y0 + syi)*WW + (x0 + 2*w);
                #pragma unroll
                for (int e = 0; e < 4; ++e)
                    *(float2*)(out + obr + (size_t)(c8*4 + e)*4*NPIX) =
                        make_float2(accp[syi*2 + 0][e], accp[syi*2 + 1][e]);
            }
        }
        __syncthreads();   // pair reads done before Qs/vs/aw rewritten
    }
}

// ---------------------------------------------------------------------------
// Launcher
// ---------------------------------------------------------------------------
extern "C" void kernel_launch(void* const* d_in, const int* in_sizes, int n_in,
                              void* d_out, int out_size)
{
    const float* x          = (const float*)d_in[0];
    const float* qkv_w      = (const float*)d_in[1];
    const float* lepe_w     = (const float*)d_in[2];
    const float* lepe_b     = (const float*)d_in[3];
    const float* bias_table = (const float*)d_in[4];
    const int*   rel_idx    = (const int*)  d_in[5];
    float* out = (float*)d_out;

    cudaFuncSetAttribute(v_kernel, cudaFuncAttributeMaxDynamicSharedMemorySize, SM_TOT_V);
    cudaFuncSetAttribute(qkv_attn_kernel, cudaFuncAttributeMaxDynamicSharedMemorySize, SM_TOT_F);

    dim3 gv(NPIX/64, NB);            // 576 x 8
    v_kernel<<<gv, 256, SM_TOT_V>>>(x, qkv_w);

    dim3 gf(WW/32, HH/2, NB);        // 6 x 96 x 8
    qkv_attn_kernel<<<gf, 256, SM_TOT_F>>>(x, qkv_w, lepe_w, lepe_b,
                                           bias_table, rel_idx, out);
}

// round 15
// speedup vs baseline: 1.5883x; 1.2140x over previous
#include <cuda_runtime.h>
#include <cuda_fp16.h>
#include <cstdint>

// ---------------------------------------------------------------------------
// Problem constants
// ---------------------------------------------------------------------------
#define HH    192
#define WW    192
#define NPIX  (HH*WW)          // 36864
#define NB    8                // 2 halves * batch 4

// ---------------------------------------------------------------------------
// Device scratch
// g_vh : v results fp16, [n(8)][head(4)][pixel][hd(32)]
// g_bw : qkv weights fp16 in mma-fragment order, [pass(3)][kstep(8)][1024 words]
// ---------------------------------------------------------------------------
__device__ __half    g_vh[8*4*NPIX*32];
__device__ uint32_t  g_bw[3*8*1024];

// ---------------------------------------------------------------------------
// fp16 helpers (base-ISA mma.sync m16n8k16)
// ---------------------------------------------------------------------------
__device__ __forceinline__ uint32_t pkh2(float a, float b) {
    __half2 h = __floats2half2_rn(a, b);   // low half = a
    return *reinterpret_cast<uint32_t*>(&h);
}
__device__ __forceinline__ void mma_f16(float* c, const uint4& a, const uint2& b) {
    asm volatile(
        "mma.sync.aligned.m16n8k16.row.col.f32.f16.f16.f32 "
        "{%0,%1,%2,%3}, {%4,%5,%6,%7}, {%8,%9}, {%0,%1,%2,%3};"
        : "+f"(c[0]), "+f"(c[1]), "+f"(c[2]), "+f"(c[3])
        : "r"(a.x), "r"(a.y), "r"(a.z), "r"(a.w), "r"(b.x), "r"(b.y));
}

// ---- fused-kernel smem map (float units) ------------------------------------
// [0 .. 4096)        A tile (64 pix x 128 k fp16 frags)
//   vs_h overlay: [0, 4896) floats = 2 heads x (4x34 halo) x 36 halves
// [4896 .. 10016)    Ks_h: 4 heads x 64 pix x 40 halves
// [10016 .. 12576)   Qs_h: 2 heads x 64 pix x 40 halves (pair)
// [12576 .. 13088)   aw: softmax weights [hp(2)][win 16][tok 4][4] fp32
// [13088 .. 13664)   lw_h: lepe weights fp16 [head][tap][hd]
// [13664 .. 13792)   lepe bias fp32 [head][hd]
// [13792 .. 13856)   attn bias fp32 [head][i*4+j]
#define SMF_KH   4896
#define SMF_QH   10016
#define SMF_AW   12576
#define SMF_LWH  13088
#define SMF_LB   13664
#define SMF_BIAS 13792
#define SM_TOT_F (13856*4)     // 55424 B -> 3 CTAs/SM

// ---- v-kernel smem map (float units) -----------------------------------------
// [0..4096) A    [4096..9216) Cs_h (4 x 64 x 40 halves = 5120 floats)
#define SMF_VC  4096
#define SM_TOT_V (9216*4)      // 36864 B

// ---------------------------------------------------------------------------
// Kernel 0: convert qkv weights fp32 [384][128] -> fp16 fragment layout g_bw.
// One thread per (pass, o, float4): 12288 threads.
// ---------------------------------------------------------------------------
__global__ void prep_bw(const float* __restrict__ qkv_w)
{
    int i = blockIdx.x*256 + threadIdx.x;   // 0..12287
    int p  = i >> 12;
    int r  = i & 4095;
    int o  = r >> 5;
    int k4 = r & 31;
    float4 v = __ldg((const float4*)(qkv_w + ((size_t)(p*128 + o))*128) + k4);
    int ks  = k4 >> 2;
    int kc  = (k4 & 3) * 4;
    int tg0 = (kc >> 1) & 3;
    int rr  = kc >> 3;
    uint32_t base = (uint32_t)(p*8192 + ks*1024 + (o>>3)*64 + ((o&7)*4 + tg0)*2 + rr);
    g_bw[base    ] = pkh2(v.x, v.y);
    g_bw[base + 2] = pkh2(v.z, v.w);
}

// ---------------------------------------------------------------------------
// Full-K MMA pass: 8 ksteps, A from smem, B fragments direct from g_bw (L1-hot)
// 8 warps: warp tile 32(M) x 32(N), M total 64
// ---------------------------------------------------------------------------
__device__ __forceinline__ void mma_pass(float acc[2][4][4],
                                         const uint32_t* __restrict__ As,
                                         const uint32_t* __restrict__ gB,
                                         int warp_m, int warp_n, int lane)
{
    #pragma unroll
    for (int kg = 0; kg < 8; ++kg) {
        uint4 a[2];
        #pragma unroll
        for (int i = 0; i < 2; ++i) {
            uint32_t u = (uint32_t)((kg*4 + warp_m*2 + i)*32 + lane);
            u ^= (u >> 3) & 7;
            a[i] = *(const uint4*)(As + (size_t)u*4);
        }
        uint2 bf[4];
        #pragma unroll
        for (int j = 0; j < 4; ++j)
            bf[j] = __ldg((const uint2*)(gB + kg*1024 + (warp_n*4 + j)*64 + lane*2));
        #pragma unroll
        for (int i = 0; i < 2; ++i)
            #pragma unroll
            for (int j = 0; j < 4; ++j)
                mma_f16(acc[i][j], a[i], bf[j]);
    }
}

__device__ __forceinline__ void acc_zero(float acc[2][4][4]) {
    #pragma unroll
    for (int i = 0; i < 2; ++i)
        #pragma unroll
        for (int j = 0; j < 4; ++j)
            #pragma unroll
            for (int e = 0; e < 4; ++e) acc[i][j][e] = 0.0f;
}

// acc -> fp16 [head(4)][pix 64][stride 40]  (Ks_h / v-kernel Cs_h)
__device__ __forceinline__ void write_kc_h(const float acc[2][4][4],
                                           __half* __restrict__ K,
                                           int warp_m, int warp_n, int lane)
{
    const int g  = lane >> 2;
    const int tg = lane & 3;
    #pragma unroll
    for (int i = 0; i < 2; ++i) {
        int pl = warp_m*32 + i*16 + g;
        #pragma unroll
        for (int j = 0; j < 4; ++j) {
            int o0 = warp_n*32 + j*8 + 2*tg;
            int h0 = o0 & 3, h1 = (o0 + 1) & 3;
            int hd = o0 >> 2;
            K[(h0*64 + pl    )*40 + hd] = __float2half_rn(acc[i][j][0]);
            K[(h1*64 + pl    )*40 + hd] = __float2half_rn(acc[i][j][1]);
            K[(h0*64 + pl + 8)*40 + hd] = __float2half_rn(acc[i][j][2]);
            K[(h1*64 + pl + 8)*40 + hd] = __float2half_rn(acc[i][j][3]);
        }
    }
}

// acc -> Qs_h fp16 [hh(2)][pix 64][40] for one head-pair
__device__ __forceinline__ void write_q_h(const float acc[2][4][4],
                                          __half* __restrict__ Q, int pair,
                                          int warp_m, int warp_n, int lane)
{
    const int g  = lane >> 2;
    const int tg = lane & 3;
    if ((tg & 1) != pair) return;
    #pragma unroll
    for (int i = 0; i < 2; ++i) {
        int pl = warp_m*32 + i*16 + g;
        #pragma unroll
        for (int j = 0; j < 4; ++j) {
            int o0 = warp_n*32 + j*8 + 2*tg;
            int hd = o0 >> 2;
            Q[(0*64 + pl    )*40 + hd] = __float2half_rn(acc[i][j][0]);
            Q[(1*64 + pl    )*40 + hd] = __float2half_rn(acc[i][j][1]);
            Q[(0*64 + pl + 8)*40 + hd] = __float2half_rn(acc[i][j][2]);
            Q[(1*64 + pl + 8)*40 + hd] = __float2half_rn(acc[i][j][3]);
        }
    }
}

// ---------------------------------------------------------------------------
// A staging: 64 pixels x 128 k -> fp16 fragment-major + swizzle.
// ---------------------------------------------------------------------------
__device__ __forceinline__ void stage_a(uint32_t* __restrict__ As,
                                        const float* __restrict__ xb,
                                        int pix, int kh)
{
    const int mtile   = pix >> 4;
    const int g       = pix & 7;
    const int rowhalf = (pix >> 3) & 1;
    #pragma unroll 4
    for (int k2 = 0; k2 < 32; k2 += 2) {
        int k = kh*32 + k2;
        float f0 = __ldg(xb + (size_t)k2 * NPIX);
        float f1 = __ldg(xb + (size_t)(k2+1) * NPIX);
        int kstep = k >> 4;
        int kc    = k & 15;
        int colhalf = kc >> 3;
        int tg      = (kc >> 1) & 3;
        uint32_t u = (uint32_t)((kstep*4 + mtile)*32 + g*4 + tg);
        u ^= (u >> 3) & 7;
        As[u*4 + colhalf*2 + rowhalf] = pkh2(f0, f1);
    }
}

// ---------------------------------------------------------------------------
// Kernel 1: v = 1x1 conv (fp16 GEMM), M=64 linear blocks.
// B fragments straight from g_bw; fp16 epilogue straight to g_vh.
// ---------------------------------------------------------------------------
__global__ void __launch_bounds__(256, 4)
v_kernel(const float* __restrict__ x)
{
    extern __shared__ __align__(16) float smf[];
    uint32_t* As   = (uint32_t*)smf;
    __half*   Cs_h = (__half*)(smf + SMF_VC);

    const int tid    = threadIdx.x;
    const int lane   = tid & 31;
    const int wid    = tid >> 5;
    const int warp_m = wid >> 2;
    const int warp_n = wid & 3;
    const int n      = blockIdx.y;
    const int half_  = n >> 2;
    const int b      = n & 3;
    const int p0     = blockIdx.x * 64;
    const size_t n4  = (size_t)n * 4;

    {
        const int pix = tid & 63;
        const int kh  = tid >> 6;
        const float* xb = x + ((size_t)(b*256 + half_*128 + kh*32)) * NPIX + p0 + pix;
        stage_a(As, xb, pix, kh);
    }
    __syncthreads();

    float acc[2][4][4];
    acc_zero(acc);
    mma_pass(acc, As, g_bw + 2*8192, warp_m, warp_n, lane);   // v weights

    write_kc_h(acc, Cs_h, warp_m, warp_n, lane);
    __syncthreads();

    // drain: one (head,pixel) row per thread, 4 x STG.128 (64B fp16) linear
    {
        int h   = tid >> 6;
        int pix = tid & 63;
        const uint4* src = (const uint4*)(Cs_h + (size_t)(h*64 + pix)*40);
        uint4* d = (uint4*)(g_vh + ((n4 + h)*NPIX + (size_t)(p0 + pix))*32);
        #pragma unroll
        for (int c = 0; c < 4; ++c) d[c] = src[c];
    }
}

// ---------------------------------------------------------------------------
// Kernel 2: fused q,k GEMM + pair-looped split-phase attention + LePE.
// CTA = 2 rows x 32 cols, 256 threads, 3 CTAs/SM.
// ---------------------------------------------------------------------------
__global__ void __launch_bounds__(256, 3)
qkv_attn_kernel(const float* __restrict__ x,
                const float* __restrict__ lepe_w, const float* __restrict__ lepe_b,
                const float* __restrict__ bias_table, const int* __restrict__ rel_idx,
                float* __restrict__ out)
{
    extern __shared__ __align__(16) float smf[];
    uint32_t* As   = (uint32_t*)smf;
    __half*   vs_h = (__half*)smf;                // overlays A after GEMMs
    __half*   Ks_h = (__half*)(smf + SMF_KH);
    __half*   Qs_h = (__half*)(smf + SMF_QH);
    __half*   lw_h = (__half*)(smf + SMF_LWH);

    const int tid    = threadIdx.x;
    const int lane   = tid & 31;
    const int wid    = tid >> 5;
    const int warp_m = wid >> 2;
    const int warp_n = wid & 3;
    const int n      = blockIdx.z;
    const int half_  = n >> 2;
    const int b      = n & 3;
    const int x0     = blockIdx.x * 32;
    const int y0     = blockIdx.y * 2;
    const size_t n4  = (size_t)n * 4;

    // stage per-head constants from raw inputs (tiny, L2-resident)
    for (int idx = tid; idx < 1152; idx += 256) {
        int head = idx / 288;
        int r    = idx % 288;
        int tap  = r >> 5;
        int hd   = r & 31;
        lw_h[idx] = __float2half_rn(__ldg(&lepe_w[(hd*4 + head)*9 + tap]));
    }
    if (tid < 128) {
        smf[SMF_LB + tid] = __ldg(&lepe_b[(tid & 31)*4 + (tid >> 5)]);
    } else if (tid < 192) {
        int t2 = tid - 128;
        int head = t2 >> 4, ij = t2 & 15;
        smf[SMF_BIAS + t2] = __ldg(&bias_table[__ldg(&rel_idx[ij])*4 + head]);
    }

    // stage A: interior 2x32 tile
    {
        const int pix = tid & 63;
        const int kh  = tid >> 6;
        const int gy  = y0 + (pix >> 5);
        const int gx  = x0 + (pix & 31);
        const float* xb = x + ((size_t)(b*256 + half_*128 + kh*32)) * NPIX
                            + (size_t)gy*WW + gx;
        stage_a(As, xb, pix, kh);
    }
    __syncthreads();

    float acc[2][4][4];

    // ---- k pass (g_bw pass 1) ----
    acc_zero(acc);
    mma_pass(acc, As, g_bw + 1*8192, warp_m, warp_n, lane);
    write_kc_h(acc, Ks_h, warp_m, warp_n, lane);

    // ---- q pass (g_bw pass 0); acc lives across the pair loop ----
    acc_zero(acc);
    mma_pass(acc, As, g_bw, warp_m, warp_n, lane);
    __syncthreads();      // A dead (vs overlay allowed); Ks complete

    const float scale = 0.17677669529663687f;  // 1/sqrt(32)

    #pragma unroll 1
    for (int pair = 0; pair < 2; ++pair) {
        // park this pair's q (fp16)
        write_q_h(acc, Qs_h, pair, warp_m, warp_n, lane);

        // stage vs_h[hh(2)][4x34 halo][36 halves] straight from fp16 g_vh
        for (int idx = tid; idx < 2*136*8; idx += 256) {
            int hh  = idx / 1088;
            int rem = idx - hh*1088;
            int pix = rem >> 3;
            int c8  = rem & 7;
            int py  = pix / 34;
            int px  = pix - py*34;
            int gy  = y0 - 1 + py;
            int gx  = x0 - 1 + px;
            uint2 p = make_uint2(0u, 0u);
            if (gy >= 0 && gy < HH && gx >= 0 && gx < WW)
                p = *(const uint2*)(g_vh +
                        ((n4 + pair*2 + hh)*NPIX + (size_t)gy*WW + gx)*32 + c8*4);
            *(uint2*)(vs_h + (size_t)(hh*136 + pix)*36 + c8*4) = p;
        }
        __syncthreads();   // Qs/vs visible

        // ---- phase 1: logits + softmax (128 thr = 2 heads x 16 win x 4 tok)
        if (tid < 128) {
            const int hp   = tid >> 6;
            const int t    = tid & 63;
            const int w    = t >> 2;
            const int i    = t & 3;
            const int head = pair*2 + hp;
            const int sy   = i >> 1, sx = i & 1;
            const int lx   = 2*w + sx;

            uint32_t qh[16];
            {
                const uint4* qp = (const uint4*)(Qs_h + (size_t)(hp*64 + sy*32 + lx)*40);
                #pragma unroll
                for (int r = 0; r < 4; ++r) *((uint4*)qh + r) = qp[r];
            }
            float lg[4];
            #pragma unroll
            for (int j = 0; j < 4; ++j) {
                const uint4* kp = (const uint4*)(Ks_h +
                    (size_t)(head*64 + (j>>1)*32 + 2*w + (j&1))*40);
                float s = 0.f;
                #pragma unroll
                for (int r = 0; r < 4; ++r) {
                    uint4 kk = kp[r];
                    const uint32_t* kw = (const uint32_t*)&kk;
                    #pragma unroll
                    for (int u = 0; u < 4; ++u) {
                        float2 kf = __half22float2(*(const __half2*)&kw[u]);
                        float2 qf = __half22float2(*(const __half2*)&qh[r*4 + u]);
                        s = fmaf(qf.x, kf.x, s);
                        s = fmaf(qf.y, kf.y, s);
                    }
                }
                lg[j] = s*scale + smf[SMF_BIAS + head*16 + i*4 + j];
            }
            float m  = fmaxf(fmaxf(lg[0], lg[1]), fmaxf(lg[2], lg[3]));
            float a0 = expf(lg[0] - m);
            float a1 = expf(lg[1] - m);
            float a2 = expf(lg[2] - m);
            float a3 = expf(lg[3] - m);
            float inv = 1.0f / (a0 + a1 + a2 + a3);
            *(float4*)(smf + SMF_AW + (size_t)(hp*16 + w)*16 + i*4) =
                make_float4(a0*inv, a1*inv, a2*inv, a3*inv);
        }
        __syncthreads();

        // ---- phase 2: tap-grid walk (256 thr = 2 heads x 16 win x 8 c8)
        {
            const int hp   = tid >> 7;
            const int rem  = tid & 127;
            const int w    = rem >> 3;
            const int c8   = rem & 7;
            const int head = pair*2 + hp;

            float a[16];
            {
                const float* awp = smf + SMF_AW + (size_t)(hp*16 + w)*16;
                #pragma unroll
                for (int r = 0; r < 4; ++r)
                    *(float4*)(a + r*4) = *(const float4*)(awp + r*4);
            }
            uint2 wvh[9];
            {
                const __half* lwp = lw_h + head*288;
                #pragma unroll
                for (int tp = 0; tp < 9; ++tp)
                    wvh[tp] = *(const uint2*)(lwp + tp*32 + c8*4);
            }
            float4 bb = *(const float4*)(smf + SMF_LB + head*32 + c8*4);

            float accp[4][4];
            #pragma unroll
            for (int i = 0; i < 4; ++i) {
                accp[i][0] = bb.x; accp[i][1] = bb.y;
                accp[i][2] = bb.z; accp[i][3] = bb.w;
            }

            const __half* vbase = vs_h + (size_t)hp*136*36;

            #pragma unroll
            for (int ty = 0; ty < 4; ++ty) {
                #pragma unroll
                for (int tx = 0; tx < 4; ++tx) {
                    const uint2 pv = *(const uint2*)(vbase +
                        (size_t)(ty*34 + 2*w + tx)*36 + c8*4);
                    float2 f01 = __half22float2(*(const __half2*)&pv.x);
                    float2 f23 = __half22float2(*(const __half2*)&pv.y);
                    float vvf[4] = {f01.x, f01.y, f23.x, f23.y};

                    if (ty >= 1 && ty <= 2 && tx >= 1 && tx <= 2) {
                        const int j = (ty - 1)*2 + (tx - 1);
                        #pragma unroll
                        for (int i = 0; i < 4; ++i) {
                            float aij = a[i*4 + j];
                            #pragma unroll
                            for (int e = 0; e < 4; ++e)
                                accp[i][e] = fmaf(aij, vvf[e], accp[i][e]);
                        }
                    }
                    #pragma unroll
                    for (int i = 0; i < 4; ++i) {
                        const int sy = i >> 1, sx = i & 1;
                        if (ty >= sy && ty <= sy + 2 && tx >= sx && tx <= sx + 2) {
                            const uint2 wh = wvh[(ty - sy)*3 + (tx - sx)];
                            float2 w01 = __half22float2(*(const __half2*)&wh.x);
                            float2 w23 = __half22float2(*(const __half2*)&wh.y);
                            accp[i][0] = fmaf(w01.x, vvf[0], accp[i][0]);
                            accp[i][1] = fmaf(w01.y, vvf[1], accp[i][1]);
                            accp[i][2] = fmaf(w23.x, vvf[2], accp[i][2]);
                            accp[i][3] = fmaf(w23.y, vvf[3], accp[i][3]);
                        }
                    }
                }
            }

            // packed float2 stores: (sx=0, sx=1) pair per row -> STG.64
            #pragma unroll
            for (int syi = 0; syi < 2; ++syi) {
                const size_t obr = ((size_t)(b*256 + half_*128 + head))*NPIX
                                 + (size_t)(y0 + syi)*WW + (x0 + 2*w);
                #pragma unroll
                for (int e = 0; e < 4; ++e)
                    *(float2*)(out + obr + (size_t)(c8*4 + e)*4*NPIX) =
                        make_float2(accp[syi*2 + 0][e], accp[syi*2 + 1][e]);
            }
        }
        __syncthreads();   // pair reads done before Qs/vs/aw rewritten
    }
}

// ---------------------------------------------------------------------------
// Launcher
// ---------------------------------------------------------------------------
extern "C" void kernel_launch(void* const* d_in, const int* in_sizes, int n_in,
                              void* d_out, int out_size)
{
    const float* x          = (const float*)d_in[0];
    const float* qkv_w      = (const float*)d_in[1];
    const float* lepe_w     = (const float*)d_in[2];
    const float* lepe_b     = (const float*)d_in[3];
    const float* bias_table = (const float*)d_in[4];
    const int*   rel_idx    = (const int*)  d_in[5];
    float* out = (float*)d_out;

    cudaFuncSetAttribute(v_kernel, cudaFuncAttributeMaxDynamicSharedMemorySize, SM_TOT_V);
    cudaFuncSetAttribute(qkv_attn_kernel, cudaFuncAttributeMaxDynamicSharedMemorySize, SM_TOT_F);

    prep_bw<<<48, 256>>>(qkv_w);

    dim3 gv(NPIX/64, NB);            // 576 x 8
    v_kernel<<<gv, 256, SM_TOT_V>>>(x);

    dim3 gf(WW/32, HH/2, NB);        // 6 x 96 x 8
    qkv_attn_kernel<<<gf, 256, SM_TOT_F>>>(x, lepe_w, lepe_b,
                                           bias_table, rel_idx, out);
}